// round 3
// baseline (speedup 1.0000x reference)
#include <cuda_runtime.h>
#include <math.h>
#include <stdint.h>

#define BATCH 16
#define SEQ   2048
#define DIM   64
#define BQ    64
#define BK    64
#define PAD   68
#define NTHREADS 256

// Flash-attention style, scalar fp32 baseline. Mask arrives as int32.
// Thread t: r = t>>2 (query row in tile), cg = t&3 (group of 16 cols/dims).
__global__ __launch_bounds__(NTHREADS, 2)
void attn_kernel(const float* __restrict__ q,
                 const float* __restrict__ k,
                 const float* __restrict__ v,
                 const int* __restrict__ mask,
                 float* __restrict__ out) {
    extern __shared__ float sm[];
    float* sQ  = sm;                  // [BQ][PAD]
    float* sKT = sQ  + BQ * PAD;      // [DIM][PAD]  (transposed: sKT[d][col])
    float* sV  = sKT + DIM * PAD;     // [BK][PAD]
    float* sP  = sV  + BK * PAD;      // [BQ][PAD]

    const int t  = threadIdx.x;
    const int b  = blockIdx.y;
    const int q0 = blockIdx.x * BQ;
    const int r  = t >> 2;
    const int cg = t & 3;

    const float* qg = q + ((size_t)b * SEQ + q0) * DIM;
    const float* kg = k + (size_t)b * SEQ * DIM;
    const float* vg = v + (size_t)b * SEQ * DIM;
    const int*   mg = mask + ((size_t)b * SEQ + (q0 + r)) * SEQ;

    // Load Q tile (coalesced float4)
    for (int i = t; i < BQ * (DIM / 4); i += NTHREADS) {
        int row = i >> 4;
        int c4  = i & 15;
        float4 val = ((const float4*)(qg + (size_t)row * DIM))[c4];
        *((float4*)(sQ + row * PAD + c4 * 4)) = val;
    }

    float m = -INFINITY;
    float l = 0.f;
    float acc[16];
#pragma unroll
    for (int j = 0; j < 16; j++) acc[j] = 0.f;

    for (int kc = 0; kc < SEQ / BK; kc++) {
        const int k0 = kc * BK;
        __syncthreads();   // previous iteration's smem reads done
        // Load K chunk transposed + V chunk
        for (int i = t; i < BK * (DIM / 4); i += NTHREADS) {
            int row = i >> 4;
            int c4  = i & 15;
            float4 kv = ((const float4*)(kg + (size_t)(k0 + row) * DIM))[c4];
            sKT[(c4 * 4 + 0) * PAD + row] = kv.x;
            sKT[(c4 * 4 + 1) * PAD + row] = kv.y;
            sKT[(c4 * 4 + 2) * PAD + row] = kv.z;
            sKT[(c4 * 4 + 3) * PAD + row] = kv.w;
            float4 vv = ((const float4*)(vg + (size_t)(k0 + row) * DIM))[c4];
            *((float4*)(sV + row * PAD + c4 * 4)) = vv;
        }
        __syncthreads();

        // Scores for this thread's 16 columns
        float sc[16];
#pragma unroll
        for (int j = 0; j < 16; j++) sc[j] = 0.f;
#pragma unroll 8
        for (int kk = 0; kk < DIM; kk++) {
            float qv = sQ[r * PAD + kk];            // broadcast within quad
            const float* kt = sKT + kk * PAD + cg * 16;
#pragma unroll
            for (int j4 = 0; j4 < 4; j4++) {
                float4 kv = *((const float4*)(kt + j4 * 4));
                sc[j4 * 4 + 0] += qv * kv.x;
                sc[j4 * 4 + 1] += qv * kv.y;
                sc[j4 * 4 + 2] += qv * kv.z;
                sc[j4 * 4 + 3] += qv * kv.w;
            }
        }

        // Mask (int32 words; fill 1e-9, NOT -inf) + temperature scale
        int mv[16];
        const int4* mrow = (const int4*)(mg + k0 + cg * 16);
#pragma unroll
        for (int j4 = 0; j4 < 4; j4++) {
            int4 mw = mrow[j4];
            mv[j4 * 4 + 0] = mw.x;
            mv[j4 * 4 + 1] = mw.y;
            mv[j4 * 4 + 2] = mw.z;
            mv[j4 * 4 + 3] = mw.w;
        }
        float cmax = -INFINITY;
#pragma unroll
        for (int j = 0; j < 16; j++) {
            float val = mv[j] ? 1e-9f : sc[j] * 0.125f;
            sc[j] = val;
            cmax = fmaxf(cmax, val);
        }
        // reduce over the 4 lanes of this quad
        cmax = fmaxf(cmax, __shfl_xor_sync(0xffffffffu, cmax, 1));
        cmax = fmaxf(cmax, __shfl_xor_sync(0xffffffffu, cmax, 2));

        float mnew = fmaxf(m, cmax);
        float corr = __expf(m - mnew);
        l *= corr;
#pragma unroll
        for (int j = 0; j < 16; j++) acc[j] *= corr;

        float psum = 0.f;
#pragma unroll
        for (int j = 0; j < 16; j++) {
            float p = __expf(sc[j] - mnew);
            psum += p;
            sP[r * PAD + cg * 16 + j] = p;
        }
        psum += __shfl_xor_sync(0xffffffffu, psum, 1);
        psum += __shfl_xor_sync(0xffffffffu, psum, 2);
        l += psum;
        m = mnew;
        __syncwarp();   // sP row written/read by same quad only

        // PV accumulate
#pragma unroll 8
        for (int kk = 0; kk < BK; kk++) {
            float p = sP[r * PAD + kk];
            const float* vp = sV + kk * PAD + cg * 16;
#pragma unroll
            for (int j4 = 0; j4 < 4; j4++) {
                float4 vv = *((const float4*)(vp + j4 * 4));
                acc[j4 * 4 + 0] += p * vv.x;
                acc[j4 * 4 + 1] += p * vv.y;
                acc[j4 * 4 + 2] += p * vv.z;
                acc[j4 * 4 + 3] += p * vv.w;
            }
        }
    }

    const float inv_l = 1.f / l;
    float* og = out + ((size_t)b * SEQ + (q0 + r)) * DIM + cg * 16;
#pragma unroll
    for (int j4 = 0; j4 < 4; j4++) {
        float4 o;
        o.x = acc[j4 * 4 + 0] * inv_l;
        o.y = acc[j4 * 4 + 1] * inv_l;
        o.z = acc[j4 * 4 + 2] * inv_l;
        o.w = acc[j4 * 4 + 3] * inv_l;
        *((float4*)(og + j4 * 4)) = o;
    }
}

extern "C" void kernel_launch(void* const* d_in, const int* in_sizes, int n_in,
                              void* d_out, int out_size) {
    const float* q = (const float*)d_in[0];
    const float* k = (const float*)d_in[1];
    const float* v = (const float*)d_in[2];
    const int*   mask = (const int*)d_in[3];
    float* out = (float*)d_out;

    const int smem_bytes = (BQ * PAD + DIM * PAD + BK * PAD + BQ * PAD) * (int)sizeof(float);
    cudaFuncSetAttribute(attn_kernel, cudaFuncAttributeMaxDynamicSharedMemorySize, smem_bytes);

    dim3 grid(SEQ / BQ, BATCH);
    attn_kernel<<<grid, NTHREADS, smem_bytes>>>(q, k, v, mask, out);
}

// round 4
// speedup vs baseline: 2.6886x; 2.6886x over previous
#include <cuda_runtime.h>
#include <math.h>
#include <stdint.h>

#define BATCH 16
#define SEQ   2048
#define DIM   64
#define BQ    64
#define BK    64
#define LDP   68          // padded row length (floats) for all smem tiles
#define NTHREADS 128

typedef unsigned long long ull;

#define FMA2(d, a, bb, c) asm("fma.rn.f32x2 %0, %1, %2, %3;" : "=l"(d) : "l"(a), "l"(bb), "l"(c))
#define MUL2(d, a, bb)    asm("mul.rn.f32x2 %0, %1, %2;"     : "=l"(d) : "l"(a), "l"(bb))
#define PACK2(d, lo, hi)  asm("mov.b64 %0, {%1, %2};"        : "=l"(d) : "f"(lo), "f"(hi))
#define UNPACK2(lo, hi, d) asm("mov.b64 {%0, %1}, %2;"       : "=f"(lo), "=f"(hi) : "l"(d))

// Flash attention, fp32, register-blocked 4x8 per thread + packed f32x2 FMA.
// Thread t: tcol = t&7 (owns cols tcol*8..+7), trow = t>>3 (owns rows trow*4..+3).
__global__ __launch_bounds__(NTHREADS, 3)
void attn_kernel(const float* __restrict__ q,
                 const float* __restrict__ k,
                 const float* __restrict__ v,
                 const int* __restrict__ mask,
                 float* __restrict__ out) {
    extern __shared__ float sm[];
    float* sQT = sm;                   // [DIM][LDP]  sQT[kk][row]
    float* sKT = sQT + DIM * LDP;      // [DIM][LDP]  sKT[kk][col]
    float* sV  = sKT + DIM * LDP;      // [BK][LDP]   sV[kk][dim]
    float* sPT = sV  + BK * LDP;       // [BK][LDP]   sPT[col][row]

    const int t    = threadIdx.x;
    const int b    = blockIdx.y;
    const int q0   = blockIdx.x * BQ;
    const int tcol = t & 7;
    const int trow = t >> 3;

    const float* qg = q + ((size_t)b * SEQ + q0) * DIM;
    const float* kg = k + (size_t)b * SEQ * DIM;
    const float* vg = v + (size_t)b * SEQ * DIM;
    const int*   mg = mask + ((size_t)b * SEQ + (q0 + trow * 4)) * SEQ + tcol * 8;

    // Load Q tile transposed: sQT[kk][row]
    for (int i = t; i < BQ * (DIM / 4); i += NTHREADS) {
        int row = i >> 4;
        int c4  = i & 15;
        float4 val = ((const float4*)(qg + (size_t)row * DIM))[c4];
        sQT[(c4 * 4 + 0) * LDP + row] = val.x;
        sQT[(c4 * 4 + 1) * LDP + row] = val.y;
        sQT[(c4 * 4 + 2) * LDP + row] = val.z;
        sQT[(c4 * 4 + 3) * LDP + row] = val.w;
    }

    float m_old[4], l_run[4];
    ull acc2[16];                      // [mi][dim-pair]
#pragma unroll
    for (int i = 0; i < 4; i++) { m_old[i] = -INFINITY; l_run[i] = 0.f; }
#pragma unroll
    for (int i = 0; i < 16; i++) acc2[i] = 0ull;

    for (int kc = 0; kc < SEQ / BK; kc++) {
        const int k0 = kc * BK;
        __syncthreads();
        // Load K transposed + V natural
        for (int i = t; i < BK * (DIM / 4); i += NTHREADS) {
            int row = i >> 4;
            int c4  = i & 15;
            float4 kv = ((const float4*)(kg + (size_t)(k0 + row) * DIM))[c4];
            sKT[(c4 * 4 + 0) * LDP + row] = kv.x;
            sKT[(c4 * 4 + 1) * LDP + row] = kv.y;
            sKT[(c4 * 4 + 2) * LDP + row] = kv.z;
            sKT[(c4 * 4 + 3) * LDP + row] = kv.w;
            float4 vv = ((const float4*)(vg + (size_t)(k0 + row) * DIM))[c4];
            *((float4*)(sV + row * LDP + c4 * 4)) = vv;
        }
        __syncthreads();

        // ---- Scores: sc2[mi][cp] over 64-deep reduction ----
        ull sc2[16];
#pragma unroll
        for (int i = 0; i < 16; i++) sc2[i] = 0ull;
#pragma unroll 4
        for (int kk = 0; kk < DIM; kk++) {
            float4 qv = *((const float4*)(sQT + kk * LDP + trow * 4));
            float4 ka = *((const float4*)(sKT + kk * LDP + tcol * 8));
            float4 kb = *((const float4*)(sKT + kk * LDP + tcol * 8 + 4));
            ull kp[4], qq[4];
            PACK2(kp[0], ka.x, ka.y); PACK2(kp[1], ka.z, ka.w);
            PACK2(kp[2], kb.x, kb.y); PACK2(kp[3], kb.z, kb.w);
            PACK2(qq[0], qv.x, qv.x); PACK2(qq[1], qv.y, qv.y);
            PACK2(qq[2], qv.z, qv.z); PACK2(qq[3], qv.w, qv.w);
#pragma unroll
            for (int mi = 0; mi < 4; mi++)
#pragma unroll
                for (int p = 0; p < 4; p++)
                    FMA2(sc2[mi * 4 + p], qq[mi], kp[p], sc2[mi * 4 + p]);
        }

        // ---- Mask (int32 words, fill 1e-9, NOT -inf), scale, online softmax ----
        float pv[4][8];
#pragma unroll
        for (int mi = 0; mi < 4; mi++) {
            const int* mrow = mg + (size_t)mi * SEQ + k0;
            int4 ma = ((const int4*)mrow)[0];
            int4 mb = ((const int4*)mrow)[1];
            float s[8];
#pragma unroll
            for (int p = 0; p < 4; p++) UNPACK2(s[2 * p], s[2 * p + 1], sc2[mi * 4 + p]);
            s[0] = ma.x ? 1e-9f : s[0] * 0.125f;
            s[1] = ma.y ? 1e-9f : s[1] * 0.125f;
            s[2] = ma.z ? 1e-9f : s[2] * 0.125f;
            s[3] = ma.w ? 1e-9f : s[3] * 0.125f;
            s[4] = mb.x ? 1e-9f : s[4] * 0.125f;
            s[5] = mb.y ? 1e-9f : s[5] * 0.125f;
            s[6] = mb.z ? 1e-9f : s[6] * 0.125f;
            s[7] = mb.w ? 1e-9f : s[7] * 0.125f;

            float cmax = s[0];
#pragma unroll
            for (int j = 1; j < 8; j++) cmax = fmaxf(cmax, s[j]);
            cmax = fmaxf(cmax, __shfl_xor_sync(0xffffffffu, cmax, 1));
            cmax = fmaxf(cmax, __shfl_xor_sync(0xffffffffu, cmax, 2));
            cmax = fmaxf(cmax, __shfl_xor_sync(0xffffffffu, cmax, 4));

            float mnew = fmaxf(m_old[mi], cmax);
            float corr = __expf(m_old[mi] - mnew);
            m_old[mi] = mnew;

            float psum = 0.f;
#pragma unroll
            for (int j = 0; j < 8; j++) {
                float p = __expf(s[j] - mnew);
                pv[mi][j] = p;
                psum += p;
            }
            psum += __shfl_xor_sync(0xffffffffu, psum, 1);
            psum += __shfl_xor_sync(0xffffffffu, psum, 2);
            psum += __shfl_xor_sync(0xffffffffu, psum, 4);
            l_run[mi] = l_run[mi] * corr + psum;

            ull c2;
            PACK2(c2, corr, corr);
#pragma unroll
            for (int p = 0; p < 4; p++) MUL2(acc2[mi * 4 + p], acc2[mi * 4 + p], c2);
        }

        // Store P transposed: sPT[col][row]
#pragma unroll
        for (int j = 0; j < 8; j++) {
            float4 w;
            w.x = pv[0][j]; w.y = pv[1][j]; w.z = pv[2][j]; w.w = pv[3][j];
            *((float4*)(sPT + (tcol * 8 + j) * LDP + trow * 4)) = w;
        }
        __syncthreads();

        // ---- PV: acc2 += P^T-tile * V over 64-deep reduction ----
#pragma unroll 4
        for (int kk = 0; kk < BK; kk++) {
            float4 pr = *((const float4*)(sPT + kk * LDP + trow * 4));
            float4 va = *((const float4*)(sV + kk * LDP + tcol * 8));
            float4 vb = *((const float4*)(sV + kk * LDP + tcol * 8 + 4));
            ull vp[4], pp[4];
            PACK2(vp[0], va.x, va.y); PACK2(vp[1], va.z, va.w);
            PACK2(vp[2], vb.x, vb.y); PACK2(vp[3], vb.z, vb.w);
            PACK2(pp[0], pr.x, pr.x); PACK2(pp[1], pr.y, pr.y);
            PACK2(pp[2], pr.z, pr.z); PACK2(pp[3], pr.w, pr.w);
#pragma unroll
            for (int mi = 0; mi < 4; mi++)
#pragma unroll
                for (int p = 0; p < 4; p++)
                    FMA2(acc2[mi * 4 + p], pp[mi], vp[p], acc2[mi * 4 + p]);
        }
    }

    // ---- Epilogue: normalize and store ----
#pragma unroll
    for (int mi = 0; mi < 4; mi++) {
        float inv_l = 1.f / l_run[mi];
        float* og = out + ((size_t)b * SEQ + (q0 + trow * 4 + mi)) * DIM + tcol * 8;
        float o[8];
#pragma unroll
        for (int p = 0; p < 4; p++) UNPACK2(o[2 * p], o[2 * p + 1], acc2[mi * 4 + p]);
        float4 wa, wb;
        wa.x = o[0] * inv_l; wa.y = o[1] * inv_l; wa.z = o[2] * inv_l; wa.w = o[3] * inv_l;
        wb.x = o[4] * inv_l; wb.y = o[5] * inv_l; wb.z = o[6] * inv_l; wb.w = o[7] * inv_l;
        *((float4*)og) = wa;
        *((float4*)(og + 4)) = wb;
    }
}

extern "C" void kernel_launch(void* const* d_in, const int* in_sizes, int n_in,
                              void* d_out, int out_size) {
    const float* q = (const float*)d_in[0];
    const float* k = (const float*)d_in[1];
    const float* v = (const float*)d_in[2];
    const int*   mask = (const int*)d_in[3];
    float* out = (float*)d_out;

    const int smem_bytes = (DIM * LDP + DIM * LDP + BK * LDP + BK * LDP) * (int)sizeof(float);
    cudaFuncSetAttribute(attn_kernel, cudaFuncAttributeMaxDynamicSharedMemorySize, smem_bytes);

    dim3 grid(SEQ / BQ, BATCH);
    attn_kernel<<<grid, NTHREADS, smem_bytes>>>(q, k, v, mask, out);
}